// round 5
// baseline (speedup 1.0000x reference)
#include <cuda_runtime.h>

#define BB 16
#define HH 512
#define WW 512

#define ROWS 8                 // rows per main tile == rows per table chunk
#define NCHK (HH / ROWS)       // 64 chunks per image column

// exclusive column-prefix table at ROWS granularity: g_tab[b][chunk][w]
__device__ float g_tab[(size_t)BB * NCHK * WW];

__device__ __forceinline__ float dgf(float t) {
    return 2.0f / (1.0f + __expf(-t));   // c=2 logistic
}

// ---------------------------------------------------------------------------
// Kernel 1: chunk-prefix table. For each (b,w): g_tab[b][c][w] = sum of
// dg_y over rows < c*ROWS.  Block: 512 thr = 32 w-lanes x 16 segs of 32 rows
// (4 chunks of 8 rows each).  Grid: BB * (WW/32) = 256 blocks.
// ---------------------------------------------------------------------------
__global__ void __launch_bounds__(512) tab_kernel(const float2* __restrict__ dg2) {
    __shared__ float segsum[16][32];
    __shared__ float segoff[16][32];

    const int b   = blockIdx.x >> 4;
    const int w0  = (blockIdx.x & 15) * 32;
    const int wl  = threadIdx.x & 31;
    const int seg = threadIdx.x >> 5;          // 0..15, 32 rows each
    const int w   = w0 + wl;
    const int h0  = seg * 32;

    const float2* base = dg2 + (size_t)b * HH * WW + w;

    float cs[4];                               // 4 chunk sums of 8 rows
    float tot = 0.f;
    #pragma unroll
    for (int c = 0; c < 4; c++) {
        float s = 0.f;
        #pragma unroll
        for (int r = 0; r < ROWS; r++)
            s += dgf(__ldg(&base[(size_t)(h0 + c * ROWS + r) * WW]).y);
        cs[c] = s;
        tot  += s;
    }
    segsum[seg][wl] = tot;
    __syncthreads();

    if (threadIdx.x < 32) {
        float a = 0.f;
        #pragma unroll
        for (int s2 = 0; s2 < 16; s2++) {
            float t = segsum[s2][threadIdx.x];
            segoff[s2][threadIdx.x] = a;       // exclusive seg prefix
            a += t;
        }
    }
    __syncthreads();

    float acc = segoff[seg][wl];
    float* t = g_tab + ((size_t)b * NCHK + seg * 4) * WW + w;
    #pragma unroll
    for (int c = 0; c < 4; c++) {
        t[(size_t)c * WW] = acc;               // exclusive chunk prefix
        acc += cs[c];
    }
}

// ---------------------------------------------------------------------------
// Kernel 2: 8-row tile per block. Loads 8 float2 rows, 8 parallel block
// scans for x_s, y_s from table + serial adds, affine, bilinear gather
// (2 rows / pass, 8 gathers in flight), grid3 staged 4 rows at a time in
// 24KB smem, two coalesced float4 writebacks.
// Grid: BB*HH/ROWS = 1024 blocks of 512 threads.
// ---------------------------------------------------------------------------
__global__ void __launch_bounds__(512, 2) main_kernel(
    const float4* __restrict__ im4,
    const float2* __restrict__ defgrad2,
    const float*  __restrict__ affine,
    float4*       __restrict__ out4,
    float*        __restrict__ grid3)
{
    __shared__ float g3[4 * WW * 3];           // 24 KB, holds 4 rows of grid3
    __shared__ float wsum[ROWS * 16];          // 512 B

    const int b  = blockIdx.x >> 6;            // / (HH/ROWS)
    const int hp = blockIdx.x & 63;
    const int h0 = hp * ROWS;
    const int w    = threadIdx.x;
    const int lane = w & 31;
    const int warp = w >> 5;

    const size_t row0 = ((size_t)b * HH + h0) * WW;

    // front-batched loads: 8 defgrad rows + table offset
    float2 d[ROWS];
    #pragma unroll
    for (int r = 0; r < ROWS; r++)
        d[r] = __ldg(defgrad2 + row0 + (size_t)r * WW + w);
    const float yoff = g_tab[((size_t)b * NCHK + hp) * WW + w];

    const float* A = affine + b * 9;
    const float a0 = __ldg(A + 0) + 1.f, a1 = __ldg(A + 1),       a2 = __ldg(A + 2);
    const float a3 = __ldg(A + 3),       a4 = __ldg(A + 4) + 1.f, a5 = __ldg(A + 5);
    const float a6 = __ldg(A + 6),       a7 = __ldg(A + 7),       a8 = __ldg(A + 8) + 1.f;

    float v[ROWS], dy[ROWS];
    #pragma unroll
    for (int r = 0; r < ROWS; r++) {
        v[r]  = dgf(d[r].x);
        dy[r] = dgf(d[r].y);
    }

    // 8 parallel block-wide inclusive scans
    #pragma unroll
    for (int o = 1; o < 32; o <<= 1) {
        float n[ROWS];
        #pragma unroll
        for (int r = 0; r < ROWS; r++) n[r] = __shfl_up_sync(0xffffffffu, v[r], o);
        if (lane >= o) {
            #pragma unroll
            for (int r = 0; r < ROWS; r++) v[r] += n[r];
        }
    }
    if (lane == 31) {
        #pragma unroll
        for (int r = 0; r < ROWS; r++) wsum[r * 16 + warp] = v[r];
    }
    __syncthreads();
    if (threadIdx.x < 128) {
        const int g = threadIdx.x >> 4, i = threadIdx.x & 15;
        float s = wsum[g * 16 + i];
        #pragma unroll
        for (int o = 1; o < 16; o <<= 1) {
            float n = __shfl_up_sync(0xffffffffu, s, o, 16);
            if (i >= o) s += n;
        }
        wsum[g * 16 + i] = s;
    }
    __syncthreads();
    float xs[ROWS];
    #pragma unroll
    for (int r = 0; r < ROWS; r++)
        xs[r] = v[r] + (warp ? wsum[r * 16 + warp - 1] : 0.f);

    const float4* imb = im4 + (size_t)b * HH * WW;

    float acc = yoff;
    #pragma unroll
    for (int half = 0; half < 2; half++) {
        #pragma unroll
        for (int q = 0; q < 2; q++) {
            const int rp = half * 4 + q * 2;   // tile-row of first of the pair
            acc += dy[rp];     const float ysA = acc;
            acc += dy[rp + 1]; const float ysB = acc;
            const float xsA = xs[rp], xsB = xs[rp + 1];

            const float x_0 = a0 * xsA + a1 * ysA + a2;
            const float y_0 = a3 * xsA + a4 * ysA + a5;
            const float z_0 = a6 * xsA + a7 * ysA + a8;
            const float x_1 = a0 * xsB + a1 * ysB + a2;
            const float y_1 = a3 * xsB + a4 * ysB + a5;
            const float z_1 = a6 * xsB + a7 * ysB + a8;

            const int fx0 = (int)floorf(x_0), fy0 = (int)floorf(y_0);
            const int fx1 = (int)floorf(x_1), fy1 = (int)floorf(y_1);
            const int x00 = min(max(fx0,     0), WW - 1);
            const int x01 = min(max(fx0 + 1, 0), WW - 1);
            const int y00 = min(max(fy0,     0), HH - 1);
            const int y01 = min(max(fy0 + 1, 0), HH - 1);
            const int x10 = min(max(fx1,     0), WW - 1);
            const int x11 = min(max(fx1 + 1, 0), WW - 1);
            const int y10 = min(max(fy1,     0), HH - 1);
            const int y11 = min(max(fy1 + 1, 0), HH - 1);

            // 8 gathers in flight
            const float4 Ia0 = __ldg(&imb[(size_t)y00 * WW + x00]);
            const float4 Ib0 = __ldg(&imb[(size_t)y01 * WW + x00]);
            const float4 Ic0 = __ldg(&imb[(size_t)y00 * WW + x01]);
            const float4 Id0 = __ldg(&imb[(size_t)y01 * WW + x01]);
            const float4 Ia1 = __ldg(&imb[(size_t)y10 * WW + x10]);
            const float4 Ib1 = __ldg(&imb[(size_t)y11 * WW + x10]);
            const float4 Ic1 = __ldg(&imb[(size_t)y10 * WW + x11]);
            const float4 Id1 = __ldg(&imb[(size_t)y11 * WW + x11]);

            // stage grid3 rows (local slot 2q, 2q+1) while gathers fly
            const int s0 = (2 * q    ) * (WW * 3) + w * 3;
            const int s1 = (2 * q + 1) * (WW * 3) + w * 3;
            g3[s0 + 0] = x_0;  g3[s0 + 1] = y_0;  g3[s0 + 2] = z_0;
            g3[s1 + 0] = x_1;  g3[s1 + 1] = y_1;  g3[s1 + 2] = z_1;

            {
                const float wx1 = (float)x01 - x_0, wx0 = x_0 - (float)x00;
                const float wy1 = (float)y01 - y_0, wy0 = y_0 - (float)y00;
                const float wa = wx1 * wy1, wb = wx1 * wy0, wc = wx0 * wy1, wd = wx0 * wy0;
                float4 o;
                o.x = wa * Ia0.x + wb * Ib0.x + wc * Ic0.x + wd * Id0.x;
                o.y = wa * Ia0.y + wb * Ib0.y + wc * Ic0.y + wd * Id0.y;
                o.z = wa * Ia0.z + wb * Ib0.z + wc * Ic0.z + wd * Id0.z;
                o.w = wa * Ia0.w + wb * Ib0.w + wc * Ic0.w + wd * Id0.w;
                out4[row0 + (size_t)rp * WW + w] = o;
            }
            {
                const float wx1 = (float)x11 - x_1, wx0 = x_1 - (float)x10;
                const float wy1 = (float)y11 - y_1, wy0 = y_1 - (float)y10;
                const float wa = wx1 * wy1, wb = wx1 * wy0, wc = wx0 * wy1, wd = wx0 * wy0;
                float4 o;
                o.x = wa * Ia1.x + wb * Ib1.x + wc * Ic1.x + wd * Id1.x;
                o.y = wa * Ia1.y + wb * Ib1.y + wc * Ic1.y + wd * Id1.y;
                o.z = wa * Ia1.z + wb * Ib1.z + wc * Ic1.z + wd * Id1.z;
                o.w = wa * Ia1.w + wb * Ib1.w + wc * Ic1.w + wd * Id1.w;
                out4[row0 + (size_t)(rp + 1) * WW + w] = o;
            }
        }

        // coalesced grid3 writeback for this half: 4*512*3 floats =
        // 1536 float4 = 3 per thread
        __syncthreads();
        {
            float4* dst = reinterpret_cast<float4*>(
                grid3 + (row0 + (size_t)(half * 4) * WW) * 3);
            const float4* src = reinterpret_cast<const float4*>(g3);
            #pragma unroll
            for (int i = 0; i < 3; i++)
                dst[threadIdx.x + i * 512] = src[threadIdx.x + i * 512];
        }
        if (half == 0) __syncthreads();        // protect g3 before re-staging
    }
}

// ---------------------------------------------------------------------------
extern "C" void kernel_launch(void* const* d_in, const int* in_sizes, int n_in,
                              void* d_out, int out_size) {
    const float4* im4      = (const float4*)d_in[0];   // [16,512,512,4] f32
    const float2* defgrad2 = (const float2*)d_in[1];   // [16,512,512,2] f32
    const float*  affine   = (const float*)d_in[2];    // [16,9] f32

    float* out   = (float*)d_out;
    float* grid3 = out + (size_t)in_sizes[0];          // out has im's element count

    tab_kernel<<<BB * (WW / 32), 512>>>(defgrad2);
    main_kernel<<<(unsigned)(BB * HH / ROWS), 512>>>(im4, defgrad2, affine,
                                                     (float4*)out, grid3);
}